// round 10
// baseline (speedup 1.0000x reference)
#include <cuda_runtime.h>
#include <cuda_fp16.h>
#include <cstdint>
#include <cstddef>

#define VN 16384
#define CN 16
#define LN 6
#define DN 64
#define TROWS (2 * VN + 1)   // 32769: [0,V)=plain, [V,2V)=negated, 2V=false_emb
#define AROWS 16512          // 129*128 padded A rows (row VN = false_emb)
#define PADK 72              // padded smem row stride (halfs): conflict-free ldmatrix

typedef unsigned long long ull;

// ---------------- device scratch ----------------
__device__ __half g_P[(size_t)LN * TROWS * 128];    // gather tables (50.3MB fp16)
__device__ __half g_ceh[(size_t)VN * CN * DN];      // clause embeddings fp16 (33.5MB)
__device__ float  g_y[(size_t)VN * 128];            // clause-combiner pre-activation
__device__ __half g_Wch[128 * 1024];                // [W1c|W2c]^T: [n][k] fp16
__device__ __half g_Ut[1536 * 64];                  // B operand [n][k]: j<6 W_l ; j>=6 Wn@W_l
__device__ __half g_varsh[(size_t)AROWS * 64];      // fp16 vars (+false row, zero pad)
__device__ float  g_c[768];                         // bias bn@W_l per col (negated half)
__device__ float  g_true[64];                       // true_emb = false_emb @ Wn + bn
__device__ int    g_flags[3];
__device__ int    g_mode;

// ---------------- helpers ----------------
__device__ __forceinline__ bool read_mask(const void* p, size_t i, int mode) {
    if (mode == 1) return ((const unsigned char*)p)[i] != 0;
    if (mode == 2) return ((const unsigned short*)p)[i] != 0;
    return ((const unsigned int*)p)[i] != 0;
}
__device__ __forceinline__ float sigf(float x) { return 1.f / (1.f + __expf(-x)); }

__device__ __forceinline__ ull mk_policy_el() {
    ull p;
    asm("createpolicy.fractional.L2::evict_last.b64 %0, 1.0;" : "=l"(p));
    return p;
}
__device__ __forceinline__ uint2 ldg_P(const __half* p, ull pol) {
    uint2 u;
    asm("ld.global.nc.L2::cache_hint.v2.b32 {%0,%1}, [%2], %3;"
        : "=r"(u.x), "=r"(u.y) : "l"(p), "l"(pol));
    return u;
}
__device__ __forceinline__ void stg_cs(__half* p, uint2 v) {
    asm volatile("st.global.cs.v2.b32 [%0], {%1,%2};"
                 :: "l"(p), "r"(v.x), "r"(v.y) : "memory");
}
__device__ __forceinline__ uint32_t smem_u32(const void* p) {
    uint32_t a;
    asm("{ .reg .u64 t; cvta.to.shared.u64 t, %1; cvt.u32.u64 %0, t; }"
        : "=r"(a) : "l"(p));
    return a;
}

// ---------------- shared HMMA warptile: 32x64 per warp over one K=64 stage ----------------
__device__ __forceinline__ void warptile_mma(uint32_t as_u32, uint32_t bs_u32,
                                             int mg, int ng, int lane,
                                             float acc[2][8][4]) {
    #pragma unroll
    for (int kc = 0; kc < 64; kc += 16) {
        uint32_t afrag[2][4];
        #pragma unroll
        for (int mt = 0; mt < 2; ++mt) {
            int row = mg * 32 + mt * 16 + (lane & 15);
            int col = kc + (lane >> 4) * 8;
            uint32_t addr = as_u32 + (uint32_t)(row * PADK + col) * 2u;
            asm volatile("ldmatrix.sync.aligned.m8n8.x4.shared.b16 {%0,%1,%2,%3}, [%4];"
                : "=r"(afrag[mt][0]), "=r"(afrag[mt][1]),
                  "=r"(afrag[mt][2]), "=r"(afrag[mt][3])
                : "r"(addr));
        }
        #pragma unroll
        for (int nt = 0; nt < 8; ++nt) {
            int rowb = ng * 64 + nt * 8 + (lane & 7);
            int colb = kc + ((lane >> 3) & 1) * 8;
            uint32_t baddr = bs_u32 + (uint32_t)(rowb * PADK + colb) * 2u;
            uint32_t b0, b1;
            asm volatile("ldmatrix.sync.aligned.m8n8.x2.shared.b16 {%0,%1}, [%2];"
                : "=r"(b0), "=r"(b1) : "r"(baddr));
            #pragma unroll
            for (int mt = 0; mt < 2; ++mt) {
                asm volatile(
                    "mma.sync.aligned.m16n8k16.row.col.f32.f16.f16.f32 "
                    "{%0,%1,%2,%3}, {%4,%5,%6,%7}, {%8,%9}, {%0,%1,%2,%3};"
                    : "+f"(acc[mt][nt][0]), "+f"(acc[mt][nt][1]),
                      "+f"(acc[mt][nt][2]), "+f"(acc[mt][nt][3])
                    : "r"(afrag[mt][0]), "r"(afrag[mt][1]),
                      "r"(afrag[mt][2]), "r"(afrag[mt][3]),
                      "r"(b0), "r"(b1));
            }
        }
    }
}

// ---------------- K0: detect boolean encoding ----------------
__global__ void k_reset() { g_flags[0] = 0; g_flags[1] = 0; g_flags[2] = 0; }

__global__ void k_scan(const unsigned int* __restrict__ w, int nwords) {
    int i = blockIdx.x * blockDim.x + threadIdx.x;
    int bad4 = 0, bad1 = 0, bad2 = 0;
    for (; i < nwords; i += gridDim.x * blockDim.x) {
        unsigned int x = w[i];
        if (!(x == 0u || x == 1u || x == 0x3F800000u)) bad4 = 1;
        if (x & 0xFEFEFEFEu) bad1 = 1;
        unsigned int h0 = x & 0xFFFFu, h1 = x >> 16;
        bool ok0 = (h0 == 0u || h0 == 0x3F80u || h0 == 0x3C00u);
        bool ok1 = (h1 == 0u || h1 == 0x3F80u || h1 == 0x3C00u);
        if (!(ok0 && ok1)) bad2 = 1;
    }
    const unsigned FULL = 0xffffffffu;
    int lane = threadIdx.x & 31;
    bad4 = __any_sync(FULL, bad4);
    bad1 = __any_sync(FULL, bad1);
    bad2 = __any_sync(FULL, bad2);
    if (lane == 0) {
        if (bad4) atomicOr(&g_flags[0], 1);
        if (bad1) atomicOr(&g_flags[1], 1);
        if (bad2) atomicOr(&g_flags[2], 1);
    }
}

__global__ void k_mode() {
    g_mode = (g_flags[0] == 0) ? 0 : ((g_flags[1] == 0) ? 1 : 2);
}

// ---------------- K1a: prep Ut / c / true_emb  (12 blocks x 256 thr, smem-tiled) ----------------
__global__ __launch_bounds__(256) void k_prep2(const float* __restrict__ W1v,
                                               const float* __restrict__ W2v,
                                               const float* __restrict__ Wn,
                                               const float* __restrict__ bn,
                                               const float* __restrict__ false_emb) {
    const int j = blockIdx.x;          // 0..11
    const int l = (j >= 6) ? j - 6 : j;
    const int tid = threadIdx.x;

    if (j < 6) {
        // Ut[(j*128+col)*64 + k] = W_l[k][col]  (transposed copy, fp32 -> fp16)
        for (int idx = tid; idx < 8192; idx += 256) {
            int col = idx >> 6, k = idx & 63;
            float v = (col < 64) ? W1v[(l * 64 + k) * 64 + col]
                                 : W2v[(l * 64 + k) * 64 + col - 64];
            g_Ut[(j * 128 + col) * 64 + k] = __float2half(v);
        }
        if (j == 0 && tid < 64) {
            float s = 0.f;
            #pragma unroll 8
            for (int m = 0; m < 64; ++m) s += false_emb[m] * Wn[m * 64 + tid];
            g_true[tid] = s + bn[tid];
        }
    } else {
        __shared__ float Wl_s[64][128];   // 32KB: W_l[m][col]
        __shared__ float Wn_s[64][64];    // 16KB: Wn[k][m]
        for (int idx = tid; idx < 8192; idx += 256) {
            int m = idx >> 7, col = idx & 127;
            Wl_s[m][col] = (col < 64) ? W1v[(l * 64 + m) * 64 + col]
                                      : W2v[(l * 64 + m) * 64 + col - 64];
        }
        for (int idx = tid; idx < 4096; idx += 256) {
            int k = idx >> 6, m = idx & 63;
            Wn_s[k][m] = Wn[k * 64 + m];
        }
        __syncthreads();

        // Ut[(j*128+col)*64 + k] = sum_m Wn[k][m] * W_l[m][col]
        const int col = tid & 127, kg = tid >> 7;   // kg in {0,1}
        #pragma unroll
        for (int kt = 0; kt < 32; ++kt) {
            int k = kg * 32 + kt;
            float s = 0.f;
            #pragma unroll 16
            for (int m = 0; m < 64; ++m) s += Wn_s[k][m] * Wl_s[m][col];
            g_Ut[(j * 128 + col) * 64 + k] = __float2half(s);
        }
        // g_c[(j-6)*128 + col] = sum_m bn[m] * W_l[m][col]
        if (tid < 128) {
            float s = 0.f;
            #pragma unroll 16
            for (int m = 0; m < 64; ++m) s += bn[m] * Wl_s[m][tid];
            g_c[(j - 6) * 128 + tid] = s;
        }
    }
}

// ---------------- K1b: vars -> fp16 padded table ----------------
__global__ __launch_bounds__(256) void k_varsh(const float* __restrict__ vars,
                                               const float* __restrict__ false_emb) {
    int idx = blockIdx.x * blockDim.x + threadIdx.x;   // one per 8 halfs
    if (idx >= AROWS * 8) return;
    int row = idx >> 3, q = idx & 7;
    __half2 h0, h1, h2, h3;
    if (row <= VN) {
        const float* src = (row < VN) ? vars + (size_t)row * 64 + q * 8
                                      : false_emb + q * 8;
        float4 f0 = *(const float4*)src;
        float4 f1 = *(const float4*)(src + 4);
        h0 = __floats2half2_rn(f0.x, f0.y); h1 = __floats2half2_rn(f0.z, f0.w);
        h2 = __floats2half2_rn(f1.x, f1.y); h3 = __floats2half2_rn(f1.z, f1.w);
    } else {
        h0 = h1 = h2 = h3 = __floats2half2_rn(0.f, 0.f);
    }
    uint4 pk;
    pk.x = *(unsigned int*)&h0; pk.y = *(unsigned int*)&h1;
    pk.z = *(unsigned int*)&h2; pk.w = *(unsigned int*)&h3;
    *(uint4*)(g_varsh + (size_t)row * 64 + q * 8) = pk;
}

// ---------------- Kw: Wch[n][k] fp16 ----------------
__global__ void k_wch(const float* __restrict__ W1c, const float* __restrict__ W2c) {
    int i = blockIdx.x * blockDim.x + threadIdx.x;
    if (i < 128 * 1024) {
        int n = i >> 10, k = i & 1023;
        float v = (n < 64) ? W1c[k * 64 + n] : W2c[k * 64 + (n - 64)];
        g_Wch[i] = __float2half(v);
    }
}

// ---------------- K1c: P table via HMMA. grid (129, 12), 256 thr ----------------
__global__ __launch_bounds__(256) void k_mma_P() {
    __shared__ __align__(16) __half As[128 * PADK];
    __shared__ __align__(16) __half Bs[128 * PADK];
    const int tid = threadIdx.x;
    const int wid = tid >> 5, lane = tid & 31;
    const int mg = wid & 3, ng = wid >> 2;
    const int j = blockIdx.y;
    const int l = (j >= 6) ? j - 6 : j;
    const bool negh = (j >= 6);
    const int r0 = blockIdx.x * 128;

    {
        int row = tid >> 1, off = (tid & 1) * 32;
        const __half* srcA = g_varsh + (size_t)(r0 + row) * 64 + off;
        const __half* srcB = g_Ut + (size_t)(j * 128 + row) * 64 + off;
        #pragma unroll
        for (int i = 0; i < 4; ++i) {
            *(uint4*)&As[row * PADK + off + i * 8] = *(const uint4*)(srcA + i * 8);
            *(uint4*)&Bs[row * PADK + off + i * 8] = *(const uint4*)(srcB + i * 8);
        }
    }
    __syncthreads();

    float acc[2][8][4];
    #pragma unroll
    for (int a = 0; a < 2; ++a)
        #pragma unroll
        for (int b = 0; b < 8; ++b)
            #pragma unroll
            for (int d = 0; d < 4; ++d) acc[a][b][d] = 0.f;

    warptile_mma(smem_u32(As), smem_u32(Bs), mg, ng, lane, acc);

    #pragma unroll
    for (int mt = 0; mt < 2; ++mt) {
        int rr = r0 + mg * 32 + mt * 16 + (lane >> 2);
        #pragma unroll
        for (int half_sel = 0; half_sel < 2; ++half_sel) {
            int rrr = rr + half_sel * 8;
            long target = -1;
            if (!negh) {
                if (rrr < VN) target = rrr;
                else if (rrr == VN) target = 2 * VN;
            } else if (rrr < VN) {
                target = (long)VN + rrr;
            }
            if (target < 0) continue;
            __half* dstrow = g_P + ((size_t)l * TROWS + target) * 128;
            #pragma unroll
            for (int nt = 0; nt < 8; ++nt) {
                int cc = ng * 64 + nt * 8 + (lane & 3) * 2;
                float v0 = acc[mt][nt][half_sel * 2 + 0];
                float v1 = acc[mt][nt][half_sel * 2 + 1];
                if (negh) { v0 += g_c[l * 128 + cc]; v1 += g_c[l * 128 + cc + 1]; }
                __half2 h = __floats2half2_rn(v0, v1);
                *(__half2*)(dstrow + cc) = h;
            }
        }
    }
}

// ---------------- K2: clause embeddings (4 clauses per warp), fp16 gathers ----------------
__global__ __launch_bounds__(256) void k_clause(const int* __restrict__ lits,
                                                const void* __restrict__ negm,
                                                const void* __restrict__ vvalid,
                                                const void* __restrict__ cvalid,
                                                const float* __restrict__ b1v,
                                                const float* __restrict__ b2v) {
    const unsigned FULL = 0xffffffffu;
    const int gw = (blockIdx.x * blockDim.x + threadIdx.x) >> 5;
    const int lane = threadIdx.x & 31;
    const int cb = gw * 4;
    if (cb >= VN * CN) return;
    const int mode = g_mode;
    const ull pol = mk_policy_el();

    int rowid[4];
    #pragma unroll
    for (int j = 0; j < 4; ++j) {
        rowid[j] = 2 * VN;
        if (lane < LN) {
            size_t bi = (size_t)(cb + j) * LN + lane;
            int idx = lits[bi];
            bool neg = read_mask(negm, bi, mode);
            bool val = read_mask(vvalid, bi, mode);
            rowid[j] = val ? (neg ? idx + VN : idx) : 2 * VN;
        }
    }

    const float* bp = (lane < 16) ? (b1v + lane * 4) : (b2v + (lane - 16) * 4);
    float4 bias = *(const float4*)bp;
    float4 acc[4] = {bias, bias, bias, bias};
    #pragma unroll
    for (int l = 0; l < LN; ++l) {
        #pragma unroll
        for (int j = 0; j < 4; ++j) {
            int r = __shfl_sync(FULL, rowid[j], l);
            uint2 u = ldg_P(g_P + ((size_t)l * TROWS + r) * 128 + lane * 4, pol);
            float2 f0 = __half22float2(*(__half2*)&u.x);
            float2 f1 = __half22float2(*(__half2*)&u.y);
            acc[j].x += f0.x; acc[j].y += f0.y; acc[j].z += f1.x; acc[j].w += f1.y;
        }
    }

    float h[4][4], ss[4];
    #pragma unroll
    for (int j = 0; j < 4; ++j) {
        float4 lin;
        lin.x = __shfl_down_sync(FULL, acc[j].x, 16);
        lin.y = __shfl_down_sync(FULL, acc[j].y, 16);
        lin.z = __shfl_down_sync(FULL, acc[j].z, 16);
        lin.w = __shfl_down_sync(FULL, acc[j].w, 16);
        float s = 0.f;
        h[j][0] = h[j][1] = h[j][2] = h[j][3] = 0.f;
        if (lane < 16) {
            h[j][0] = sigf(acc[j].x) + lin.x;
            h[j][1] = sigf(acc[j].y) + lin.y;
            h[j][2] = sigf(acc[j].z) + lin.z;
            h[j][3] = sigf(acc[j].w) + lin.w;
            s = h[j][0]*h[j][0] + h[j][1]*h[j][1] + h[j][2]*h[j][2] + h[j][3]*h[j][3];
        }
        ss[j] = s;
    }
    #pragma unroll
    for (int o = 16; o; o >>= 1) {
        #pragma unroll
        for (int j = 0; j < 4; ++j) ss[j] += __shfl_xor_sync(FULL, ss[j], o);
    }

    #pragma unroll
    for (int j = 0; j < 4; ++j) {
        float inv = rsqrtf(ss[j]);
        bool cv = read_mask(cvalid, (size_t)(cb + j), mode);
        if (lane < 16) {
            float4 o4;
            if (cv) o4 = make_float4(h[j][0]*inv, h[j][1]*inv, h[j][2]*inv, h[j][3]*inv);
            else    o4 = *(const float4*)(g_true + lane * 4);
            __half2 p0 = __floats2half2_rn(o4.x, o4.y);
            __half2 p1 = __floats2half2_rn(o4.z, o4.w);
            uint2 w;
            w.x = *(unsigned int*)&p0; w.y = *(unsigned int*)&p1;
            stg_cs(g_ceh + (size_t)(cb + j) * 64 + lane * 4, w);
        }
    }
}

// ---------------- K3: [V,1024](fp16) @ Wch^T -> g_y via HMMA. grid 128, 256 thr ----------------
__global__ __launch_bounds__(256) void k_gemm() {
    __shared__ __align__(16) __half As[128 * PADK];
    __shared__ __align__(16) __half Bs[128 * PADK];
    const int tid = threadIdx.x;
    const int wid = tid >> 5, lane = tid & 31;
    const int mg = wid & 3, ng = wid >> 2;
    const int r0 = blockIdx.x * 128;

    float acc[2][8][4];
    #pragma unroll
    for (int a = 0; a < 2; ++a)
        #pragma unroll
        for (int b = 0; b < 8; ++b)
            #pragma unroll
            for (int d = 0; d < 4; ++d) acc[a][b][d] = 0.f;

    const int row = tid >> 1, off = (tid & 1) * 32;
    for (int kc = 0; kc < 1024; kc += 64) {
        const __half* srcA = g_ceh + (size_t)(r0 + row) * 1024 + kc + off;
        const __half* srcB = g_Wch + (size_t)row * 1024 + kc + off;
        #pragma unroll
        for (int i = 0; i < 4; ++i) {
            *(uint4*)&As[row * PADK + off + i * 8] = *(const uint4*)(srcA + i * 8);
            *(uint4*)&Bs[row * PADK + off + i * 8] = *(const uint4*)(srcB + i * 8);
        }
        __syncthreads();
        warptile_mma(smem_u32(As), smem_u32(Bs), mg, ng, lane, acc);
        __syncthreads();
    }

    #pragma unroll
    for (int mt = 0; mt < 2; ++mt) {
        int r1 = r0 + mg * 32 + mt * 16 + (lane >> 2);
        #pragma unroll
        for (int nt = 0; nt < 8; ++nt) {
            int cc = ng * 64 + nt * 8 + (lane & 3) * 2;
            *(float2*)(g_y + (size_t)r1 * 128 + cc) =
                make_float2(acc[mt][nt][0], acc[mt][nt][1]);
            *(float2*)(g_y + (size_t)(r1 + 8) * 128 + cc) =
                make_float2(acc[mt][nt][2], acc[mt][nt][3]);
        }
    }
}

// ---------------- K4: final combine + normalize + passthrough ----------------
__global__ __launch_bounds__(256) void k_final(const float* __restrict__ vars,
                                               const void* __restrict__ cvalid,
                                               const float* __restrict__ b1c,
                                               const float* __restrict__ b2c,
                                               float* __restrict__ out) {
    const unsigned FULL = 0xffffffffu;
    const int gw = (blockIdx.x * blockDim.x + threadIdx.x) >> 5;
    const int lane = threadIdx.x & 31;
    if (gw >= VN) return;
    const int mode = g_mode;

    const float* bp = (lane < 16) ? (b1c + lane * 4) : (b2c + (lane - 16) * 4);
    float4 acc = *(const float4*)bp;
    float4 yv = *(const float4*)(g_y + (size_t)gw * 128 + lane * 4);
    acc.x += yv.x; acc.y += yv.y; acc.z += yv.z; acc.w += yv.w;

    float4 lin;
    lin.x = __shfl_down_sync(FULL, acc.x, 16);
    lin.y = __shfl_down_sync(FULL, acc.y, 16);
    lin.z = __shfl_down_sync(FULL, acc.z, 16);
    lin.w = __shfl_down_sync(FULL, acc.w, 16);

    float hx = 0.f, hy = 0.f, hz = 0.f, hw = 0.f, ss = 0.f;
    if (lane < 16) {
        hx = sigf(acc.x) + lin.x;
        hy = sigf(acc.y) + lin.y;
        hz = sigf(acc.z) + lin.z;
        hw = sigf(acc.w) + lin.w;
        ss = hx * hx + hy * hy + hz * hz + hw * hw;
    }
    #pragma unroll
    for (int o = 16; o; o >>= 1) ss += __shfl_xor_sync(FULL, ss, o);
    float inv = rsqrtf(ss);

    bool cv = (lane < 16) ? read_mask(cvalid, (size_t)gw * CN + lane, mode) : false;
    bool has = __ballot_sync(FULL, cv) != 0u;

    if (lane < 16) {
        float4 o4;
        if (has) {
            o4 = make_float4(hx * inv, hy * inv, hz * inv, hw * inv);
        } else {
            o4 = *(const float4*)(vars + (size_t)gw * 64 + lane * 4);
        }
        *(float4*)(out + (size_t)gw * 64 + lane * 4) = o4;
    }
}

// ---------------- launch ----------------
extern "C" void kernel_launch(void* const* d_in, const int* in_sizes, int n_in,
                              void* d_out, int out_size) {
    const float* vars      = (const float*)d_in[0];
    const int*   lits      = (const int*)d_in[1];
    const void*  negm      = d_in[2];
    const void*  vval      = d_in[3];
    const void*  cval      = d_in[4];
    const float* Wn        = (const float*)d_in[5];
    const float* bn        = (const float*)d_in[6];
    const float* false_emb = (const float*)d_in[7];
    const float* W1v       = (const float*)d_in[8];
    const float* b1v       = (const float*)d_in[9];
    const float* W2v       = (const float*)d_in[10];
    const float* b2v       = (const float*)d_in[11];
    const float* W1c       = (const float*)d_in[12];
    const float* b1c       = (const float*)d_in[13];
    const float* W2c       = (const float*)d_in[14];
    const float* b2c       = (const float*)d_in[15];
    float* out = (float*)d_out;

    // K0: boolean encoding detection
    k_reset<<<1, 1>>>();
    const int nwords = (VN * CN * LN) / 4;
    k_scan<<<1024, 256>>>((const unsigned int*)negm, nwords);
    k_mode<<<1, 1>>>();

    // K1: weight prep (smem-tiled) + fp16 vars + P table via HMMA
    k_prep2<<<12, 256>>>(W1v, W2v, Wn, bn, false_emb);
    k_varsh<<<(AROWS * 8 + 255) / 256, 256>>>(vars, false_emb);
    k_wch<<<(128 * 1024 + 255) / 256, 256>>>(W1c, W2c);
    k_mma_P<<<dim3(129, 12), 256>>>();

    // K2: clause embeddings via fp16 gather-and-add
    k_clause<<<(VN * CN) / 32, 256>>>(lits, negm, vval, cval, b1v, b2v);

    // K3: clause combiner GEMM via HMMA
    k_gemm<<<VN / 128, 256>>>();

    // K4: final residual combine + normalize + passthrough
    k_final<<<VN / 8, 256>>>(vars, cval, b1c, b2c, out);
}

// round 11
// speedup vs baseline: 1.1307x; 1.1307x over previous
#include <cuda_runtime.h>
#include <cuda_fp16.h>
#include <cstdint>
#include <cstddef>

#define VN 16384
#define CN 16
#define LN 6
#define DN 64
#define TROWS (2 * VN + 1)   // 32769: [0,V)=plain, [V,2V)=negated, 2V=false_emb
#define AROWS 16512          // 129*128 padded A rows (row VN = false_emb)
#define PADK 72              // padded smem row stride (halfs): conflict-free ldmatrix

typedef unsigned long long ull;

// ---------------- device scratch ----------------
__device__ __half g_P[(size_t)LN * TROWS * 128];    // gather tables (50.3MB fp16)
__device__ __half g_ceh[(size_t)VN * CN * DN];      // clause embeddings fp16 (33.5MB)
__device__ float  g_y[(size_t)VN * 128];            // clause-combiner pre-activation
__device__ __half g_Wch[128 * 1024];                // [W1c|W2c]^T: [n][k] fp16
__device__ __half g_Ut[1536 * 64];                  // B operand [n][k]: j<6 W_l ; j>=6 Wn@W_l
__device__ __half g_varsh[(size_t)AROWS * 64];      // fp16 vars (+false row, zero pad)
__device__ float  g_WnT[64 * 64];                   // Wn transposed: WnT[m][k] = Wn[k][m]
__device__ float  g_c[768];                         // bias bn@W_l per col (negated half)
__device__ float  g_true[64];                       // true_emb = false_emb @ Wn + bn
__device__ int    g_flags[3];
__device__ int    g_mode;

// ---------------- helpers ----------------
__device__ __forceinline__ bool read_mask(const void* p, size_t i, int mode) {
    if (mode == 1) return ((const unsigned char*)p)[i] != 0;
    if (mode == 2) return ((const unsigned short*)p)[i] != 0;
    return ((const unsigned int*)p)[i] != 0;
}
__device__ __forceinline__ float sigf(float x) { return 1.f / (1.f + __expf(-x)); }

__device__ __forceinline__ ull mk_policy_el() {
    ull p;
    asm("createpolicy.fractional.L2::evict_last.b64 %0, 1.0;" : "=l"(p));
    return p;
}
__device__ __forceinline__ uint2 ldg_P(const __half* p, ull pol) {
    uint2 u;
    asm("ld.global.nc.L2::cache_hint.v2.b32 {%0,%1}, [%2], %3;"
        : "=r"(u.x), "=r"(u.y) : "l"(p), "l"(pol));
    return u;
}
__device__ __forceinline__ void stg_cs(__half* p, uint2 v) {
    asm volatile("st.global.cs.v2.b32 [%0], {%1,%2};"
                 :: "l"(p), "r"(v.x), "r"(v.y) : "memory");
}
__device__ __forceinline__ uint32_t smem_u32(const void* p) {
    uint32_t a;
    asm("{ .reg .u64 t; cvta.to.shared.u64 t, %1; cvt.u32.u64 %0, t; }"
        : "=r"(a) : "l"(p));
    return a;
}

// ---------------- shared HMMA warptile: 32x64 per warp over one K=64 stage ----------------
__device__ __forceinline__ void warptile_mma(uint32_t as_u32, uint32_t bs_u32,
                                             int mg, int ng, int lane,
                                             float acc[2][8][4]) {
    #pragma unroll
    for (int kc = 0; kc < 64; kc += 16) {
        uint32_t afrag[2][4];
        #pragma unroll
        for (int mt = 0; mt < 2; ++mt) {
            int row = mg * 32 + mt * 16 + (lane & 15);
            int col = kc + (lane >> 4) * 8;
            uint32_t addr = as_u32 + (uint32_t)(row * PADK + col) * 2u;
            asm volatile("ldmatrix.sync.aligned.m8n8.x4.shared.b16 {%0,%1,%2,%3}, [%4];"
                : "=r"(afrag[mt][0]), "=r"(afrag[mt][1]),
                  "=r"(afrag[mt][2]), "=r"(afrag[mt][3])
                : "r"(addr));
        }
        #pragma unroll
        for (int nt = 0; nt < 8; ++nt) {
            int rowb = ng * 64 + nt * 8 + (lane & 7);
            int colb = kc + ((lane >> 3) & 1) * 8;
            uint32_t baddr = bs_u32 + (uint32_t)(rowb * PADK + colb) * 2u;
            uint32_t b0, b1;
            asm volatile("ldmatrix.sync.aligned.m8n8.x2.shared.b16 {%0,%1}, [%2];"
                : "=r"(b0), "=r"(b1) : "r"(baddr));
            #pragma unroll
            for (int mt = 0; mt < 2; ++mt) {
                asm volatile(
                    "mma.sync.aligned.m16n8k16.row.col.f32.f16.f16.f32 "
                    "{%0,%1,%2,%3}, {%4,%5,%6,%7}, {%8,%9}, {%0,%1,%2,%3};"
                    : "+f"(acc[mt][nt][0]), "+f"(acc[mt][nt][1]),
                      "+f"(acc[mt][nt][2]), "+f"(acc[mt][nt][3])
                    : "r"(afrag[mt][0]), "r"(afrag[mt][1]),
                      "r"(afrag[mt][2]), "r"(afrag[mt][3]),
                      "r"(b0), "r"(b1));
            }
        }
    }
}

// ---------------- K0a: reset flags + transpose Wn ----------------
__global__ __launch_bounds__(256) void k_init(const float* __restrict__ Wn) {
    int tid = threadIdx.x;
    if (tid == 0) { g_flags[0] = 0; g_flags[1] = 0; g_flags[2] = 0; }
    #pragma unroll
    for (int t = 0; t < 16; ++t) {
        int i = tid + t * 256;          // i = m*64 + k
        int m = i >> 6, k = i & 63;
        g_WnT[i] = Wn[k * 64 + m];
    }
}

__global__ void k_scan(const unsigned int* __restrict__ w, int nwords) {
    int i = blockIdx.x * blockDim.x + threadIdx.x;
    int bad4 = 0, bad1 = 0, bad2 = 0;
    for (; i < nwords; i += gridDim.x * blockDim.x) {
        unsigned int x = w[i];
        if (!(x == 0u || x == 1u || x == 0x3F800000u)) bad4 = 1;
        if (x & 0xFEFEFEFEu) bad1 = 1;
        unsigned int h0 = x & 0xFFFFu, h1 = x >> 16;
        bool ok0 = (h0 == 0u || h0 == 0x3F80u || h0 == 0x3C00u);
        bool ok1 = (h1 == 0u || h1 == 0x3F80u || h1 == 0x3C00u);
        if (!(ok0 && ok1)) bad2 = 1;
    }
    const unsigned FULL = 0xffffffffu;
    int lane = threadIdx.x & 31;
    bad4 = __any_sync(FULL, bad4);
    bad1 = __any_sync(FULL, bad1);
    bad2 = __any_sync(FULL, bad2);
    if (lane == 0) {
        if (bad4) atomicOr(&g_flags[0], 1);
        if (bad1) atomicOr(&g_flags[1], 1);
        if (bad2) atomicOr(&g_flags[2], 1);
    }
}

__global__ void k_mode() {
    g_mode = (g_flags[0] == 0) ? 0 : ((g_flags[1] == 0) ? 1 : 2);
}

// ---------------- K1: fused prep (Ut/c/true + varsh + Wch) ----------------
// blocks [0,384): Ut prep (4 cols per block, one output per thread)
// blocks [384,900): varsh ; blocks [900,1412): Wch ; block 1412: true_emb
#define PB_UT   384
#define PB_VARS 516
#define PB_WCH  512
__global__ __launch_bounds__(256) void k_prepall(const float* __restrict__ vars,
                                                 const float* __restrict__ false_emb,
                                                 const float* __restrict__ Wn,
                                                 const float* __restrict__ bn,
                                                 const float* __restrict__ W1v,
                                                 const float* __restrict__ W2v,
                                                 const float* __restrict__ W1c,
                                                 const float* __restrict__ W2c) {
    const int b = blockIdx.x;
    const int tid = threadIdx.x;

    if (b < PB_UT) {
        // one Ut output per thread: n = b*4 + tid/64, k = tid%64
        const int n = b * 4 + (tid >> 6);
        const int k = tid & 63;
        const int j = n >> 7, col = n & 127;
        const int l = (j >= 6) ? j - 6 : j;
        float v;
        if (j < 6) {
            v = (col < 64) ? W1v[(l * 64 + k) * 64 + col]
                           : W2v[(l * 64 + k) * 64 + col - 64];
        } else {
            float s0 = 0.f, s1 = 0.f;
            #pragma unroll 8
            for (int m = 0; m < 64; m += 2) {
                float wl0 = (col < 64) ? W1v[(l * 64 + m) * 64 + col]
                                       : W2v[(l * 64 + m) * 64 + col - 64];
                float wl1 = (col < 64) ? W1v[(l * 64 + m + 1) * 64 + col]
                                       : W2v[(l * 64 + m + 1) * 64 + col - 64];
                s0 += g_WnT[m * 64 + k] * wl0;        // coalesced across lanes (k)
                s1 += g_WnT[(m + 1) * 64 + k] * wl1;
            }
            v = s0 + s1;
            if (k == 0) {   // g_c for this column
                float s = 0.f;
                #pragma unroll 16
                for (int m = 0; m < 64; ++m) {
                    float wl = (col < 64) ? W1v[(l * 64 + m) * 64 + col]
                                          : W2v[(l * 64 + m) * 64 + col - 64];
                    s += bn[m] * wl;
                }
                g_c[(j - 6) * 128 + col] = s;
            }
        }
        g_Ut[n * 64 + k] = __float2half(v);
    } else if (b < PB_UT + PB_VARS) {
        // varsh: fp16 vars (+false row, zero pad), one uint4 (8 halfs) per thread
        int idx = (b - PB_UT) * 256 + tid;
        if (idx < AROWS * 8) {
            int row = idx >> 3, q = idx & 7;
            __half2 h0, h1, h2, h3;
            if (row <= VN) {
                const float* src = (row < VN) ? vars + (size_t)row * 64 + q * 8
                                              : false_emb + q * 8;
                float4 f0 = *(const float4*)src;
                float4 f1 = *(const float4*)(src + 4);
                h0 = __floats2half2_rn(f0.x, f0.y); h1 = __floats2half2_rn(f0.z, f0.w);
                h2 = __floats2half2_rn(f1.x, f1.y); h3 = __floats2half2_rn(f1.z, f1.w);
            } else {
                h0 = h1 = h2 = h3 = __floats2half2_rn(0.f, 0.f);
            }
            uint4 pk;
            pk.x = *(unsigned int*)&h0; pk.y = *(unsigned int*)&h1;
            pk.z = *(unsigned int*)&h2; pk.w = *(unsigned int*)&h3;
            *(uint4*)(g_varsh + (size_t)row * 64 + q * 8) = pk;
        }
    } else if (b < PB_UT + PB_VARS + PB_WCH) {
        // Wch[n][k] fp16
        int i = (b - PB_UT - PB_VARS) * 256 + tid;
        if (i < 128 * 1024) {
            int n = i >> 10, k = i & 1023;
            float v = (n < 64) ? W1c[k * 64 + n] : W2c[k * 64 + (n - 64)];
            g_Wch[i] = __float2half(v);
        }
    } else {
        // true_emb
        if (tid < 64) {
            float s = 0.f;
            #pragma unroll 8
            for (int m = 0; m < 64; ++m) s += false_emb[m] * Wn[m * 64 + tid];
            g_true[tid] = s + bn[tid];
        }
    }
}

// ---------------- K1c: P table via HMMA. grid (129, 12), 256 thr ----------------
__global__ __launch_bounds__(256) void k_mma_P() {
    __shared__ __align__(16) __half As[128 * PADK];
    __shared__ __align__(16) __half Bs[128 * PADK];
    const int tid = threadIdx.x;
    const int wid = tid >> 5, lane = tid & 31;
    const int mg = wid & 3, ng = wid >> 2;
    const int j = blockIdx.y;
    const int l = (j >= 6) ? j - 6 : j;
    const bool negh = (j >= 6);
    const int r0 = blockIdx.x * 128;

    {
        int row = tid >> 1, off = (tid & 1) * 32;
        const __half* srcA = g_varsh + (size_t)(r0 + row) * 64 + off;
        const __half* srcB = g_Ut + (size_t)(j * 128 + row) * 64 + off;
        #pragma unroll
        for (int i = 0; i < 4; ++i) {
            *(uint4*)&As[row * PADK + off + i * 8] = *(const uint4*)(srcA + i * 8);
            *(uint4*)&Bs[row * PADK + off + i * 8] = *(const uint4*)(srcB + i * 8);
        }
    }
    __syncthreads();

    float acc[2][8][4];
    #pragma unroll
    for (int a = 0; a < 2; ++a)
        #pragma unroll
        for (int b = 0; b < 8; ++b)
            #pragma unroll
            for (int d = 0; d < 4; ++d) acc[a][b][d] = 0.f;

    warptile_mma(smem_u32(As), smem_u32(Bs), mg, ng, lane, acc);

    #pragma unroll
    for (int mt = 0; mt < 2; ++mt) {
        int rr = r0 + mg * 32 + mt * 16 + (lane >> 2);
        #pragma unroll
        for (int half_sel = 0; half_sel < 2; ++half_sel) {
            int rrr = rr + half_sel * 8;
            long target = -1;
            if (!negh) {
                if (rrr < VN) target = rrr;
                else if (rrr == VN) target = 2 * VN;
            } else if (rrr < VN) {
                target = (long)VN + rrr;
            }
            if (target < 0) continue;
            __half* dstrow = g_P + ((size_t)l * TROWS + target) * 128;
            #pragma unroll
            for (int nt = 0; nt < 8; ++nt) {
                int cc = ng * 64 + nt * 8 + (lane & 3) * 2;
                float v0 = acc[mt][nt][half_sel * 2 + 0];
                float v1 = acc[mt][nt][half_sel * 2 + 1];
                if (negh) { v0 += g_c[l * 128 + cc]; v1 += g_c[l * 128 + cc + 1]; }
                __half2 h = __floats2half2_rn(v0, v1);
                *(__half2*)(dstrow + cc) = h;
            }
        }
    }
}

// ---------------- K2: clause embeddings (4 clauses per warp), fp16 gathers ----------------
__global__ __launch_bounds__(256) void k_clause(const int* __restrict__ lits,
                                                const void* __restrict__ negm,
                                                const void* __restrict__ vvalid,
                                                const void* __restrict__ cvalid,
                                                const float* __restrict__ b1v,
                                                const float* __restrict__ b2v) {
    const unsigned FULL = 0xffffffffu;
    const int gw = (blockIdx.x * blockDim.x + threadIdx.x) >> 5;
    const int lane = threadIdx.x & 31;
    const int cb = gw * 4;
    if (cb >= VN * CN) return;
    const int mode = g_mode;
    const ull pol = mk_policy_el();

    int rowid[4];
    #pragma unroll
    for (int j = 0; j < 4; ++j) {
        rowid[j] = 2 * VN;
        if (lane < LN) {
            size_t bi = (size_t)(cb + j) * LN + lane;
            int idx = lits[bi];
            bool neg = read_mask(negm, bi, mode);
            bool val = read_mask(vvalid, bi, mode);
            rowid[j] = val ? (neg ? idx + VN : idx) : 2 * VN;
        }
    }

    const float* bp = (lane < 16) ? (b1v + lane * 4) : (b2v + (lane - 16) * 4);
    float4 bias = *(const float4*)bp;
    float4 acc[4] = {bias, bias, bias, bias};
    #pragma unroll
    for (int l = 0; l < LN; ++l) {
        #pragma unroll
        for (int j = 0; j < 4; ++j) {
            int r = __shfl_sync(FULL, rowid[j], l);
            uint2 u = ldg_P(g_P + ((size_t)l * TROWS + r) * 128 + lane * 4, pol);
            float2 f0 = __half22float2(*(__half2*)&u.x);
            float2 f1 = __half22float2(*(__half2*)&u.y);
            acc[j].x += f0.x; acc[j].y += f0.y; acc[j].z += f1.x; acc[j].w += f1.y;
        }
    }

    float h[4][4], ss[4];
    #pragma unroll
    for (int j = 0; j < 4; ++j) {
        float4 lin;
        lin.x = __shfl_down_sync(FULL, acc[j].x, 16);
        lin.y = __shfl_down_sync(FULL, acc[j].y, 16);
        lin.z = __shfl_down_sync(FULL, acc[j].z, 16);
        lin.w = __shfl_down_sync(FULL, acc[j].w, 16);
        float s = 0.f;
        h[j][0] = h[j][1] = h[j][2] = h[j][3] = 0.f;
        if (lane < 16) {
            h[j][0] = sigf(acc[j].x) + lin.x;
            h[j][1] = sigf(acc[j].y) + lin.y;
            h[j][2] = sigf(acc[j].z) + lin.z;
            h[j][3] = sigf(acc[j].w) + lin.w;
            s = h[j][0]*h[j][0] + h[j][1]*h[j][1] + h[j][2]*h[j][2] + h[j][3]*h[j][3];
        }
        ss[j] = s;
    }
    #pragma unroll
    for (int o = 16; o; o >>= 1) {
        #pragma unroll
        for (int j = 0; j < 4; ++j) ss[j] += __shfl_xor_sync(FULL, ss[j], o);
    }

    #pragma unroll
    for (int j = 0; j < 4; ++j) {
        float inv = rsqrtf(ss[j]);
        bool cv = read_mask(cvalid, (size_t)(cb + j), mode);
        if (lane < 16) {
            float4 o4;
            if (cv) o4 = make_float4(h[j][0]*inv, h[j][1]*inv, h[j][2]*inv, h[j][3]*inv);
            else    o4 = *(const float4*)(g_true + lane * 4);
            __half2 p0 = __floats2half2_rn(o4.x, o4.y);
            __half2 p1 = __floats2half2_rn(o4.z, o4.w);
            uint2 w;
            w.x = *(unsigned int*)&p0; w.y = *(unsigned int*)&p1;
            stg_cs(g_ceh + (size_t)(cb + j) * 64 + lane * 4, w);
        }
    }
}

// ---------------- K3: [V,1024](fp16) @ Wch^T -> g_y via HMMA. grid 128, 256 thr ----------------
__global__ __launch_bounds__(256) void k_gemm() {
    __shared__ __align__(16) __half As[128 * PADK];
    __shared__ __align__(16) __half Bs[128 * PADK];
    const int tid = threadIdx.x;
    const int wid = tid >> 5, lane = tid & 31;
    const int mg = wid & 3, ng = wid >> 2;
    const int r0 = blockIdx.x * 128;

    float acc[2][8][4];
    #pragma unroll
    for (int a = 0; a < 2; ++a)
        #pragma unroll
        for (int b = 0; b < 8; ++b)
            #pragma unroll
            for (int d = 0; d < 4; ++d) acc[a][b][d] = 0.f;

    const int row = tid >> 1, off = (tid & 1) * 32;
    for (int kc = 0; kc < 1024; kc += 64) {
        const __half* srcA = g_ceh + (size_t)(r0 + row) * 1024 + kc + off;
        const __half* srcB = g_Wch + (size_t)row * 1024 + kc + off;
        #pragma unroll
        for (int i = 0; i < 4; ++i) {
            *(uint4*)&As[row * PADK + off + i * 8] = *(const uint4*)(srcA + i * 8);
            *(uint4*)&Bs[row * PADK + off + i * 8] = *(const uint4*)(srcB + i * 8);
        }
        __syncthreads();
        warptile_mma(smem_u32(As), smem_u32(Bs), mg, ng, lane, acc);
        __syncthreads();
    }

    #pragma unroll
    for (int mt = 0; mt < 2; ++mt) {
        int r1 = r0 + mg * 32 + mt * 16 + (lane >> 2);
        #pragma unroll
        for (int nt = 0; nt < 8; ++nt) {
            int cc = ng * 64 + nt * 8 + (lane & 3) * 2;
            *(float2*)(g_y + (size_t)r1 * 128 + cc) =
                make_float2(acc[mt][nt][0], acc[mt][nt][1]);
            *(float2*)(g_y + (size_t)(r1 + 8) * 128 + cc) =
                make_float2(acc[mt][nt][2], acc[mt][nt][3]);
        }
    }
}

// ---------------- K4: final combine + normalize + passthrough ----------------
__global__ __launch_bounds__(256) void k_final(const float* __restrict__ vars,
                                               const void* __restrict__ cvalid,
                                               const float* __restrict__ b1c,
                                               const float* __restrict__ b2c,
                                               float* __restrict__ out) {
    const unsigned FULL = 0xffffffffu;
    const int gw = (blockIdx.x * blockDim.x + threadIdx.x) >> 5;
    const int lane = threadIdx.x & 31;
    if (gw >= VN) return;
    const int mode = g_mode;

    const float* bp = (lane < 16) ? (b1c + lane * 4) : (b2c + (lane - 16) * 4);
    float4 acc = *(const float4*)bp;
    float4 yv = *(const float4*)(g_y + (size_t)gw * 128 + lane * 4);
    acc.x += yv.x; acc.y += yv.y; acc.z += yv.z; acc.w += yv.w;

    float4 lin;
    lin.x = __shfl_down_sync(FULL, acc.x, 16);
    lin.y = __shfl_down_sync(FULL, acc.y, 16);
    lin.z = __shfl_down_sync(FULL, acc.z, 16);
    lin.w = __shfl_down_sync(FULL, acc.w, 16);

    float hx = 0.f, hy = 0.f, hz = 0.f, hw = 0.f, ss = 0.f;
    if (lane < 16) {
        hx = sigf(acc.x) + lin.x;
        hy = sigf(acc.y) + lin.y;
        hz = sigf(acc.z) + lin.z;
        hw = sigf(acc.w) + lin.w;
        ss = hx * hx + hy * hy + hz * hz + hw * hw;
    }
    #pragma unroll
    for (int o = 16; o; o >>= 1) ss += __shfl_xor_sync(FULL, ss, o);
    float inv = rsqrtf(ss);

    bool cv = (lane < 16) ? read_mask(cvalid, (size_t)gw * CN + lane, mode) : false;
    bool has = __ballot_sync(FULL, cv) != 0u;

    if (lane < 16) {
        float4 o4;
        if (has) {
            o4 = make_float4(hx * inv, hy * inv, hz * inv, hw * inv);
        } else {
            o4 = *(const float4*)(vars + (size_t)gw * 64 + lane * 4);
        }
        *(float4*)(out + (size_t)gw * 64 + lane * 4) = o4;
    }
}

// ---------------- launch ----------------
extern "C" void kernel_launch(void* const* d_in, const int* in_sizes, int n_in,
                              void* d_out, int out_size) {
    const float* vars      = (const float*)d_in[0];
    const int*   lits      = (const int*)d_in[1];
    const void*  negm      = d_in[2];
    const void*  vval      = d_in[3];
    const void*  cval      = d_in[4];
    const float* Wn        = (const float*)d_in[5];
    const float* bn        = (const float*)d_in[6];
    const float* false_emb = (const float*)d_in[7];
    const float* W1v       = (const float*)d_in[8];
    const float* b1v       = (const float*)d_in[9];
    const float* W2v       = (const float*)d_in[10];
    const float* b2v       = (const float*)d_in[11];
    const float* W1c       = (const float*)d_in[12];
    const float* b1c       = (const float*)d_in[13];
    const float* W2c       = (const float*)d_in[14];
    const float* b2c       = (const float*)d_in[15];
    float* out = (float*)d_out;

    // K0: init (flags + Wn transpose) + boolean encoding detection
    k_init<<<1, 256>>>(Wn);
    const int nwords = (VN * CN * LN) / 4;
    k_scan<<<1024, 256>>>((const unsigned int*)negm, nwords);
    k_mode<<<1, 1>>>();

    // K1: fused prep (Ut + varsh + Wch + true_emb), then P table via HMMA
    k_prepall<<<PB_UT + PB_VARS + PB_WCH + 1, 256>>>(vars, false_emb, Wn, bn,
                                                     W1v, W2v, W1c, W2c);
    k_mma_P<<<dim3(129, 12), 256>>>();

    // K2: clause embeddings via fp16 gather-and-add
    k_clause<<<(VN * CN) / 32, 256>>>(lits, negm, vval, cval, b1v, b2v);

    // K3: clause combiner GEMM via HMMA
    k_gemm<<<VN / 128, 256>>>();

    // K4: final residual combine + normalize + passthrough
    k_final<<<VN / 8, 256>>>(vars, cval, b1c, b2c, out);
}